// round 2
// baseline (speedup 1.0000x reference)
#include <cuda_runtime.h>
#include <cuda_bf16.h>
#include <math.h>

// ---------------------------------------------------------------------------
// VQ-VAE forward, fp32, NCHW. B=8, HID=256, ZC=64, K=512.
// Pipeline:
//  c1: conv 3->256 k4 s2 p1, relu         [8,3,128,128] -> [8,256,64,64]
//  c2: conv 256->256 k4 s2 p1, relu       -> [8,256,32,32]
//  2x res: h += conv1x1(relu(conv3x3(relu(h))))
//  to_z: conv1x1 256->64                  -> z_e [8,64,32,32]
//  VQ: argmin over 512 codes (C=64)       -> ids, e_k
//  from_z: conv1x1 64->256, relu
//  t1: convT 256->256 k4 s2 p1, relu      -> [8,256,64,64]
//  t2: convT 256->3 k4 s2 p1, sigmoid     -> [8,3,128,128]
// Output packing (float32, concatenated): out | z_e | e_k | ids
// ---------------------------------------------------------------------------

#define B 8
#define HID 256
#define ZC 64
#define KCODES 512

// output offsets (floats)
#define OUT_OFF 0
#define OUT_N   (8*3*128*128)       // 393216
#define ZE_OFF  (OUT_OFF + OUT_N)   // 393216
#define ZE_N    (8*64*32*32)        // 524288
#define EK_OFF  (ZE_OFF + ZE_N)     // 917504
#define EK_N    (8*64*32*32)        // 524288
#define IDS_OFF (EK_OFF + EK_N)     // 1441792

// scratch
__device__ float g_h1[8u*256u*64u*64u];   // h1 (enc) / d1 (dec)  33.5 MB
__device__ float g_h2[8u*256u*32u*32u];   // h                     8.4 MB
__device__ float g_r [8u*256u*32u*32u];   // r tmp / d0            8.4 MB
__device__ float g_z [8u*64u*32u*32u];    // z_e                   2.1 MB
__device__ float g_ek[8u*64u*32u*32u];    // e_k                   2.1 MB

// ---------------------------------------------------------------------------
// c1: 3->256, k4 s2 p1, input 128x128, output 64x64, relu.
// grid (B*64, 16), block (64,4). Each thread: 1 pixel x 4 oc.
// ---------------------------------------------------------------------------
__global__ void k_c1(const float* __restrict__ x, const float* __restrict__ w,
                     const float* __restrict__ bias)
{
    int b  = blockIdx.x >> 6;
    int oy = blockIdx.x & 63;
    int oc0 = blockIdx.y * 16;
    int tx = threadIdx.x;            // 0..63 = ox
    int ty = threadIdx.y;            // 0..3
    int tid = ty * 64 + tx;

    __shared__ float s_in[3][4][130];
    __shared__ float s_w[16][48];

    for (int e = tid; e < 3 * 4 * 130; e += 256) {
        int c = e / (4 * 130);
        int rem = e % (4 * 130);
        int ky = rem / 130, col = rem % 130;
        int iy = 2 * oy - 1 + ky;
        int ix = col - 1;
        float v = 0.f;
        if (iy >= 0 && iy < 128 && ix >= 0 && ix < 128)
            v = x[((b * 3 + c) * 128 + iy) * 128 + ix];
        s_in[c][ky][col] = v;
    }
    for (int e = tid; e < 16 * 48; e += 256) {
        int o = e / 48, r = e % 48;
        s_w[o][r] = w[(oc0 + o) * 48 + r];
    }
    __syncthreads();

    float acc[4] = {0.f, 0.f, 0.f, 0.f};
    #pragma unroll
    for (int c = 0; c < 3; c++)
        #pragma unroll
        for (int ky = 0; ky < 4; ky++)
            #pragma unroll
            for (int kx = 0; kx < 4; kx++) {
                float v = s_in[c][ky][2 * tx + kx];
                int r = (c * 4 + ky) * 4 + kx;
                #pragma unroll
                for (int j = 0; j < 4; j++)
                    acc[j] += s_w[ty * 4 + j][r] * v;
            }

    #pragma unroll
    for (int j = 0; j < 4; j++) {
        int oc = oc0 + ty * 4 + j;
        float v = acc[j] + bias[oc];
        g_h1[((size_t)(b * 256 + oc) * 64 + oy) * 64 + tx] = fmaxf(v, 0.f);
    }
}

// ---------------------------------------------------------------------------
// c2: 256->256, k4 s2 p1, input 64x64, output 32x32, relu.
// grid (B*32, 4), block (32,8). Each thread: 1 pixel x 8 oc.
// ---------------------------------------------------------------------------
__global__ void k_c2(const float* __restrict__ w, const float* __restrict__ bias)
{
    int b  = blockIdx.x >> 5;
    int oy = blockIdx.x & 31;
    int oc0 = blockIdx.y * 64;
    int tx = threadIdx.x;            // ox
    int ty = threadIdx.y;
    int tid = ty * 32 + tx;

    __shared__ float s_in[8][4][66];
    __shared__ float s_w[64][128];

    float acc[8];
    #pragma unroll
    for (int j = 0; j < 8; j++) acc[j] = 0.f;

    for (int c0 = 0; c0 < 256; c0 += 8) {
        __syncthreads();
        for (int e = tid; e < 8 * 4 * 66; e += 256) {
            int c = e / (4 * 66);
            int rem = e % (4 * 66);
            int ky = rem / 66, col = rem % 66;
            int iy = 2 * oy - 1 + ky;
            int ix = col - 1;
            float v = 0.f;
            if (iy >= 0 && iy < 64 && ix >= 0 && ix < 64)
                v = g_h1[((size_t)(b * 256 + c0 + c) * 64 + iy) * 64 + ix];
            s_in[c][ky][col] = v;
        }
        for (int e = tid; e < 64 * 128; e += 256) {
            int o = e >> 7, r = e & 127;
            s_w[o][r] = w[(size_t)(oc0 + o) * 4096 + c0 * 16 + r];
        }
        __syncthreads();

        #pragma unroll 4
        for (int r = 0; r < 128; r++) {
            int c = r >> 4;
            int ky = (r >> 2) & 3;
            int kx = r & 3;
            float v = s_in[c][ky][2 * tx + kx];
            #pragma unroll
            for (int j = 0; j < 8; j++)
                acc[j] += s_w[ty * 8 + j][r] * v;
        }
    }

    #pragma unroll
    for (int j = 0; j < 8; j++) {
        int oc = oc0 + ty * 8 + j;
        float v = acc[j] + bias[oc];
        g_h2[((size_t)(b * 256 + oc) * 32 + oy) * 32 + tx] = fmaxf(v, 0.f);
    }
}

// ---------------------------------------------------------------------------
// res conv3x3: r = conv3x3(relu(h2), w) + b, pad 1, no out relu.
// grid (B*32, 4), block (32,8).
// ---------------------------------------------------------------------------
__global__ void k_res3(const float* __restrict__ w, const float* __restrict__ bias)
{
    int b  = blockIdx.x >> 5;
    int oy = blockIdx.x & 31;
    int oc0 = blockIdx.y * 64;
    int tx = threadIdx.x;
    int ty = threadIdx.y;
    int tid = ty * 32 + tx;

    __shared__ float s_in[8][3][34];
    __shared__ float s_w[64][72];

    float acc[8];
    #pragma unroll
    for (int j = 0; j < 8; j++) acc[j] = 0.f;

    for (int c0 = 0; c0 < 256; c0 += 8) {
        __syncthreads();
        for (int e = tid; e < 8 * 3 * 34; e += 256) {
            int c = e / (3 * 34);
            int rem = e % (3 * 34);
            int ky = rem / 34, col = rem % 34;
            int iy = oy - 1 + ky;
            int ix = col - 1;
            float v = 0.f;
            if (iy >= 0 && iy < 32 && ix >= 0 && ix < 32)
                v = fmaxf(g_h2[((size_t)(b * 256 + c0 + c) * 32 + iy) * 32 + ix], 0.f);
            s_in[c][ky][col] = v;
        }
        for (int e = tid; e < 64 * 72; e += 256) {
            int o = e / 72, r = e % 72;
            s_w[o][r] = w[(size_t)(oc0 + o) * 2304 + c0 * 9 + r];
        }
        __syncthreads();

        #pragma unroll
        for (int c = 0; c < 8; c++)
            #pragma unroll
            for (int ky = 0; ky < 3; ky++)
                #pragma unroll
                for (int kx = 0; kx < 3; kx++) {
                    float v = s_in[c][ky][tx + kx];
                    int r = c * 9 + ky * 3 + kx;
                    #pragma unroll
                    for (int j = 0; j < 8; j++)
                        acc[j] += s_w[ty * 8 + j][r] * v;
                }
    }

    #pragma unroll
    for (int j = 0; j < 8; j++) {
        int oc = oc0 + ty * 8 + j;
        g_r[((size_t)(b * 256 + oc) * 32 + oy) * 32 + tx] = acc[j] + bias[oc];
    }
}

// ---------------------------------------------------------------------------
// conv1x1 (GEMM over 1024 pixels/batch). grid (B*8, cout/64), block (32,8).
// Each thread: 4 pixels x 8 oc.
// ---------------------------------------------------------------------------
template<int CIN, int INRELU, int OUTRELU, int ADDRES>
__global__ void k_conv1(const float* __restrict__ in, const float* __restrict__ w,
                        const float* __restrict__ bias, const float* __restrict__ res,
                        float* __restrict__ out, float* __restrict__ out2, int cout)
{
    int b  = blockIdx.x >> 3;
    int pt = blockIdx.x & 7;
    int oc0 = blockIdx.y * 64;
    int tx = threadIdx.x;
    int ty = threadIdx.y;
    int tid = ty * 32 + tx;
    int px0 = pt * 128;

    __shared__ float s_in[16][128];
    __shared__ float s_w[64][16];

    float acc[8][4];
    #pragma unroll
    for (int j = 0; j < 8; j++)
        #pragma unroll
        for (int m = 0; m < 4; m++) acc[j][m] = 0.f;

    for (int c0 = 0; c0 < CIN; c0 += 16) {
        __syncthreads();
        for (int e = tid; e < 2048; e += 256) {
            int i = e >> 7, p = e & 127;
            float v = in[(size_t)(b * CIN + c0 + i) * 1024 + px0 + p];
            if (INRELU) v = fmaxf(v, 0.f);
            s_in[i][p] = v;
        }
        for (int e = tid; e < 1024; e += 256) {
            int o = e >> 4, i = e & 15;
            s_w[o][i] = w[(size_t)(oc0 + o) * CIN + c0 + i];
        }
        __syncthreads();

        #pragma unroll
        for (int i = 0; i < 16; i++) {
            float v0 = s_in[i][tx];
            float v1 = s_in[i][tx + 32];
            float v2 = s_in[i][tx + 64];
            float v3 = s_in[i][tx + 96];
            #pragma unroll
            for (int j = 0; j < 8; j++) {
                float wv = s_w[ty * 8 + j][i];
                acc[j][0] += wv * v0;
                acc[j][1] += wv * v1;
                acc[j][2] += wv * v2;
                acc[j][3] += wv * v3;
            }
        }
    }

    #pragma unroll
    for (int j = 0; j < 8; j++) {
        int oc = oc0 + ty * 8 + j;
        float bv = bias[oc];
        #pragma unroll
        for (int m = 0; m < 4; m++) {
            size_t idx = (size_t)(b * cout + oc) * 1024 + px0 + tx + 32 * m;
            float v = acc[j][m] + bv;
            if (ADDRES) v += res[idx];
            if (OUTRELU) v = fmaxf(v, 0.f);
            out[idx] = v;
            if (out2) out2[idx] = v;
        }
    }
}

// ---------------------------------------------------------------------------
// VQ: per position, argmin_k ||z - c_k||^2 over 512 codes (C=64).
// grid (64), block (128). Codebook staged in smem in 4 chunks of 128 codes.
// ---------------------------------------------------------------------------
__global__ void k_vq(const float* __restrict__ codebook, float* __restrict__ d_out)
{
    int pos = blockIdx.x * 128 + threadIdx.x;   // 0..8191
    int b   = pos >> 10;
    int hw  = pos & 1023;

    float z[64];
    float z2 = 0.f;
    #pragma unroll
    for (int c = 0; c < 64; c++) {
        z[c] = g_z[(size_t)(b * 64 + c) * 1024 + hw];
        z2 += z[c] * z[c];
    }

    __shared__ float s_cb[128][64];
    __shared__ float s_n[128];

    float best = INFINITY;
    int bestk = 0;
    for (int k0 = 0; k0 < 512; k0 += 128) {
        __syncthreads();
        for (int e = threadIdx.x; e < 128 * 64; e += 128)
            s_cb[e >> 6][e & 63] = codebook[k0 * 64 + e];
        __syncthreads();
        {
            float n = 0.f;
            #pragma unroll
            for (int c = 0; c < 64; c++) {
                float cv = s_cb[threadIdx.x][c];
                n += cv * cv;
            }
            s_n[threadIdx.x] = n;
        }
        __syncthreads();
        for (int k = 0; k < 128; k++) {
            float dot = 0.f;
            #pragma unroll
            for (int c = 0; c < 64; c++)
                dot += z[c] * s_cb[k][c];
            float d = (z2 - 2.f * dot) + s_n[k];
            if (d < best) { best = d; bestk = k0 + k; }
        }
    }

    d_out[IDS_OFF + pos] = (float)bestk;
    const float* crow = codebook + (size_t)bestk * 64;
    #pragma unroll
    for (int c = 0; c < 64; c++) {
        float v = crow[c];
        size_t idx = (size_t)(b * 64 + c) * 1024 + hw;
        g_ek[idx] = v;
        d_out[EK_OFF + idx] = v;
    }
}

// ---------------------------------------------------------------------------
// t1: convT 256->256 k4 s2 p1, input 32x32 -> output 64x64, relu.
// grid (B*64, 4), block (32,8). Each thread: ox pair (2tx, 2tx+1) x 8 oc.
// w layout: [ic][oc][ky][kx].
// ---------------------------------------------------------------------------
__global__ void k_t1(const float* __restrict__ w, const float* __restrict__ bias)
{
    int b  = blockIdx.x >> 6;
    int oy = blockIdx.x & 63;
    int oc0 = blockIdx.y * 64;
    int tx = threadIdx.x;
    int ty = threadIdx.y;
    int tid = ty * 32 + tx;

    int iy0, ky0, iy1, ky1;
    if (oy & 1) { iy0 = (oy + 1) >> 1; ky0 = 0; iy1 = (oy - 1) >> 1; ky1 = 2; }
    else        { iy0 = oy >> 1;       ky0 = 1; iy1 = (oy >> 1) - 1; ky1 = 3; }

    __shared__ float s_in[8][2][34];
    __shared__ float s_w[8][64][16];

    float acc[8][2];
    #pragma unroll
    for (int j = 0; j < 8; j++) { acc[j][0] = 0.f; acc[j][1] = 0.f; }

    for (int c0 = 0; c0 < 256; c0 += 8) {
        __syncthreads();
        for (int e = tid; e < 8 * 2 * 34; e += 256) {
            int c = e / 68;
            int rem = e % 68;
            int rr = rem / 34, col = rem % 34;
            int iy = rr ? iy1 : iy0;
            int ix = col - 1;
            float v = 0.f;
            if (iy >= 0 && iy < 32 && ix >= 0 && ix < 32)
                v = g_r[((size_t)(b * 256 + c0 + c) * 32 + iy) * 32 + ix];
            s_in[c][rr][col] = v;
        }
        for (int e = tid; e < 8192; e += 256) {
            int c = e >> 10;
            int rem = e & 1023;
            int o = rem >> 4, r = rem & 15;
            s_w[c][o][r] = w[((size_t)(c0 + c) * 256 + oc0 + o) * 16 + r];
        }
        __syncthreads();

        #pragma unroll
        for (int c = 0; c < 8; c++)
            #pragma unroll
            for (int rr = 0; rr < 2; rr++) {
                float a  = s_in[c][rr][tx];      // ix = tx-1
                float bb = s_in[c][rr][tx + 1];  // ix = tx
                float cc = s_in[c][rr][tx + 2];  // ix = tx+1
                int ky = rr ? ky1 : ky0;
                #pragma unroll
                for (int j = 0; j < 8; j++) {
                    const float* wr = s_w[c][ty * 8 + j];
                    acc[j][0] += wr[ky * 4 + 3] * a  + wr[ky * 4 + 1] * bb;
                    acc[j][1] += wr[ky * 4 + 0] * cc + wr[ky * 4 + 2] * bb;
                }
            }
    }

    #pragma unroll
    for (int j = 0; j < 8; j++) {
        int oc = oc0 + ty * 8 + j;
        float bv = bias[oc];
        #pragma unroll
        for (int p = 0; p < 2; p++) {
            float v = acc[j][p] + bv;
            g_h1[((size_t)(b * 256 + oc) * 64 + oy) * 64 + 2 * tx + p] = fmaxf(v, 0.f);
        }
    }
}

// ---------------------------------------------------------------------------
// t2: convT 256->3 k4 s2 p1, input 64x64 -> output 128x128, sigmoid -> d_out.
// grid (B*128), block (64). Each thread: ox pair x 3 oc.
// w layout: [ic][oc][ky][kx], oc=3.
// ---------------------------------------------------------------------------
__global__ void k_t2(const float* __restrict__ w, const float* __restrict__ bias,
                     float* __restrict__ out)
{
    int b  = blockIdx.x >> 7;
    int oy = blockIdx.x & 127;
    int tx = threadIdx.x;            // 0..63

    int iy0, ky0, iy1, ky1;
    if (oy & 1) { iy0 = (oy + 1) >> 1; ky0 = 0; iy1 = (oy - 1) >> 1; ky1 = 2; }
    else        { iy0 = oy >> 1;       ky0 = 1; iy1 = (oy >> 1) - 1; ky1 = 3; }

    __shared__ float s_in[16][2][66];
    __shared__ float s_w[16][3][16];

    float acc[3][2];
    #pragma unroll
    for (int o = 0; o < 3; o++) { acc[o][0] = 0.f; acc[o][1] = 0.f; }

    for (int c0 = 0; c0 < 256; c0 += 16) {
        __syncthreads();
        for (int e = tx; e < 16 * 2 * 66; e += 64) {
            int c = e / 132;
            int rem = e % 132;
            int rr = rem / 66, col = rem % 66;
            int iy = rr ? iy1 : iy0;
            int ix = col - 1;
            float v = 0.f;
            if (iy >= 0 && iy < 64 && ix >= 0 && ix < 64)
                v = g_h1[((size_t)(b * 256 + c0 + c) * 64 + iy) * 64 + ix];
            s_in[c][rr][col] = v;
        }
        for (int e = tx; e < 16 * 3 * 16; e += 64) {
            int c = e / 48;
            int rem = e % 48;
            int o = rem / 16, r = rem % 16;
            s_w[c][o][r] = w[((size_t)(c0 + c) * 3 + o) * 16 + r];
        }
        __syncthreads();

        #pragma unroll
        for (int c = 0; c < 16; c++)
            #pragma unroll
            for (int rr = 0; rr < 2; rr++) {
                float a  = s_in[c][rr][tx];
                float bb = s_in[c][rr][tx + 1];
                float cc = s_in[c][rr][tx + 2];
                int ky = rr ? ky1 : ky0;
                #pragma unroll
                for (int o = 0; o < 3; o++) {
                    const float* wr = s_w[c][o];
                    acc[o][0] += wr[ky * 4 + 3] * a  + wr[ky * 4 + 1] * bb;
                    acc[o][1] += wr[ky * 4 + 0] * cc + wr[ky * 4 + 2] * bb;
                }
            }
    }

    #pragma unroll
    for (int o = 0; o < 3; o++) {
        float bv = bias[o];
        #pragma unroll
        for (int p = 0; p < 2; p++) {
            float v = acc[o][p] + bv;
            float s = 1.f / (1.f + expf(-v));
            out[((size_t)(b * 3 + o) * 128 + oy) * 128 + 2 * tx + p] = s;
        }
    }
}

// ---------------------------------------------------------------------------
// launch
// ---------------------------------------------------------------------------
extern "C" void kernel_launch(void* const* d_in, const int* in_sizes, int n_in,
                              void* d_out, int out_size)
{
    const float* x       = (const float*)d_in[0];
    const float* c1_w    = (const float*)d_in[1];
    const float* c1_b    = (const float*)d_in[2];
    const float* c2_w    = (const float*)d_in[3];
    const float* c2_b    = (const float*)d_in[4];
    const float* r0_w3   = (const float*)d_in[5];
    const float* r0_b3   = (const float*)d_in[6];
    const float* r0_w1   = (const float*)d_in[7];
    const float* r0_b1   = (const float*)d_in[8];
    const float* r1_w3   = (const float*)d_in[9];
    const float* r1_b3   = (const float*)d_in[10];
    const float* r1_w1   = (const float*)d_in[11];
    const float* r1_b1   = (const float*)d_in[12];
    const float* to_z_w  = (const float*)d_in[13];
    const float* to_z_b  = (const float*)d_in[14];
    const float* codebook= (const float*)d_in[15];
    const float* from_z_w= (const float*)d_in[16];
    const float* from_z_b= (const float*)d_in[17];
    const float* t1_w    = (const float*)d_in[18];
    const float* t1_b    = (const float*)d_in[19];
    const float* t2_w    = (const float*)d_in[20];
    const float* t2_b    = (const float*)d_in[21];

    float* out = (float*)d_out;

    float* p_h2 = nullptr;
    float* p_r  = nullptr;
    float* p_z  = nullptr;
    float* p_ek = nullptr;
    cudaGetSymbolAddress((void**)&p_h2, g_h2);
    cudaGetSymbolAddress((void**)&p_r,  g_r);
    cudaGetSymbolAddress((void**)&p_z,  g_z);
    cudaGetSymbolAddress((void**)&p_ek, g_ek);

    // encoder
    k_c1<<<dim3(B * 64, 16), dim3(64, 4)>>>(x, c1_w, c1_b);
    k_c2<<<dim3(B * 32, 4), dim3(32, 8)>>>(c2_w, c2_b);

    // residual blocks
    k_res3<<<dim3(B * 32, 4), dim3(32, 8)>>>(r0_w3, r0_b3);
    k_conv1<256, 1, 0, 1><<<dim3(B * 8, 4), dim3(32, 8)>>>(
        p_r, r0_w1, r0_b1, p_h2, p_h2, nullptr, 256);
    k_res3<<<dim3(B * 32, 4), dim3(32, 8)>>>(r1_w3, r1_b3);
    k_conv1<256, 1, 0, 1><<<dim3(B * 8, 4), dim3(32, 8)>>>(
        p_r, r1_w1, r1_b1, p_h2, p_h2, nullptr, 256);

    // to_z -> z_e (scratch + output copy)
    k_conv1<256, 0, 0, 0><<<dim3(B * 8, 1), dim3(32, 8)>>>(
        p_h2, to_z_w, to_z_b, nullptr, p_z, out + ZE_OFF, 64);

    // vector quantization -> ids, e_k (scratch + output copy)
    k_vq<<<64, 128>>>(codebook, out);

    // decoder
    k_conv1<64, 0, 1, 0><<<dim3(B * 8, 4), dim3(32, 8)>>>(
        p_ek, from_z_w, from_z_b, nullptr, p_r, nullptr, 256);
    k_t1<<<dim3(B * 64, 4), dim3(32, 8)>>>(t1_w, t1_b);
    k_t2<<<dim3(B * 128), dim3(64)>>>(t2_w, t2_b, out + OUT_OFF);

    (void)in_sizes; (void)n_in; (void)out_size;
}

// round 3
// speedup vs baseline: 1.1893x; 1.1893x over previous
#include <cuda_runtime.h>
#include <cuda_bf16.h>
#include <math.h>

// VQ-VAE fwd fp32 NCHW. Output: out | z_e | e_k | ids (float32 concat)
#define B 8
#define OUT_N   (8*3*128*128)
#define ZE_OFF  OUT_N
#define ZE_N    (8*64*32*32)
#define EK_OFF  (ZE_OFF + ZE_N)
#define IDS_OFF (EK_OFF + ZE_N)

typedef unsigned long long u64;
#define FMA2(d, a, b) asm("fma.rn.f32x2 %0, %1, %2, %0;" : "+l"(d) : "l"(a), "l"(b))
__device__ __forceinline__ float2 unpack2(u64 v) {
    float2 r; asm("mov.b64 {%0, %1}, %2;" : "=f"(r.x), "=f"(r.y) : "l"(v)); return r;
}

__device__ float g_h1[8u*256u*64u*64u];
__device__ float g_h2[8u*256u*32u*32u];
__device__ float g_r [8u*256u*32u*32u];
__device__ float g_z [8u*64u*32u*32u];
__device__ float g_ek[8u*64u*32u*32u];

// ---------------- c1: 3->256 k4 s2 p1, 128->64, relu (small) ----------------
__global__ void k_c1(const float* __restrict__ x, const float* __restrict__ w,
                     const float* __restrict__ bias)
{
    int b  = blockIdx.x >> 6;
    int oy = blockIdx.x & 63;
    int oc0 = blockIdx.y * 16;
    int tx = threadIdx.x, ty = threadIdx.y;
    int tid = ty * 64 + tx;

    __shared__ float s_in[3][4][130];
    __shared__ float s_w[16][48];

    for (int e = tid; e < 3*4*130; e += 256) {
        int c = e / 520, rem = e % 520;
        int ky = rem / 130, col = rem % 130;
        int iy = 2*oy - 1 + ky, ix = col - 1;
        float v = 0.f;
        if (iy >= 0 && iy < 128 && ix >= 0 && ix < 128)
            v = x[((b*3 + c)*128 + iy)*128 + ix];
        s_in[c][ky][col] = v;
    }
    for (int e = tid; e < 768; e += 256)
        s_w[e / 48][e % 48] = w[(oc0 + e/48)*48 + e%48];
    __syncthreads();

    float acc[4] = {0.f, 0.f, 0.f, 0.f};
    #pragma unroll
    for (int c = 0; c < 3; c++)
        #pragma unroll
        for (int ky = 0; ky < 4; ky++)
            #pragma unroll
            for (int kx = 0; kx < 4; kx++) {
                float v = s_in[c][ky][2*tx + kx];
                int r = (c*4 + ky)*4 + kx;
                #pragma unroll
                for (int j = 0; j < 4; j++) acc[j] += s_w[ty*4 + j][r] * v;
            }
    #pragma unroll
    for (int j = 0; j < 4; j++) {
        int oc = oc0 + ty*4 + j;
        g_h1[((size_t)(b*256 + oc)*64 + oy)*64 + tx] = fmaxf(acc[j] + bias[oc], 0.f);
    }
}

// ---------------- c2: 256->256 k4 s2 p1, 64->32, relu (f32x2) ---------------
// grid (64, 8), block 128. oc tile 32 (warp=8 oc), px tile 32x4.
__global__ void __launch_bounds__(128) k_c2(const float* __restrict__ w,
                                            const float* __restrict__ bias)
{
    int b   = blockIdx.x >> 3;
    int oy0 = (blockIdx.x & 7) * 4;
    int oc0 = blockIdx.y * 32;
    int tid = threadIdx.x;
    int lane = tid & 31, warp = tid >> 5;
    int ocw = warp * 8;

    __shared__ __align__(16) float2 s_in[4][10][2][34]; // [ic][row][parity][j] dup
    __shared__ __align__(16) float  s_w[4][16][36];     // [ic][tap][oc] pad36

    u64 acc[2][2][4] = {};

    for (int c0 = 0; c0 < 256; c0 += 4) {
        __syncthreads();
        for (int e = tid; e < 2640; e += 128) {
            int c = e / 660, rem = e % 660;
            int r = rem / 66;
            int ix = rem % 66 - 1;
            int iy = 2*oy0 - 1 + r;
            float v = 0.f;
            if (iy >= 0 && iy < 64 && ix >= 0 && ix < 64)
                v = g_h1[((size_t)(b*256 + c0 + c)*64 + iy)*64 + ix];
            s_in[c][r][ix & 1][(ix + (ix & 1)) >> 1] = make_float2(v, v);
        }
        for (int e = tid; e < 512; e += 128) {
            int o = e >> 4, c = (e >> 2) & 3, t4 = (e & 3) * 4;
            float4 wv = *(const float4*)&w[(size_t)(oc0 + o)*4096 + (c0 + c)*16 + t4];
            s_w[c][t4+0][o] = wv.x; s_w[c][t4+1][o] = wv.y;
            s_w[c][t4+2][o] = wv.z; s_w[c][t4+3][o] = wv.w;
        }
        __syncthreads();

        #pragma unroll 1
        for (int c = 0; c < 4; c++) {
            #pragma unroll
            for (int ky = 0; ky < 4; ky++) {
                #pragma unroll
                for (int kx = 0; kx < 4; kx++) {
                    int p = (kx & 1) ^ 1;        // kx even -> odd-ix plane
                    int j = lane + (kx >> 1);
                    u64 v0 = *(const u64*)&s_in[c][2*0 + ky][p][j];
                    u64 v1 = *(const u64*)&s_in[c][2*1 + ky][p][j];
                    u64 v2 = *(const u64*)&s_in[c][2*2 + ky][p][j];
                    u64 v3 = *(const u64*)&s_in[c][2*3 + ky][p][j];
                    #pragma unroll
                    for (int jj = 0; jj < 2; jj++) {
                        ulonglong2 wp = *(const ulonglong2*)&s_w[c][ky*4 + kx][ocw + 4*jj];
                        FMA2(acc[jj][0][0], wp.x, v0); FMA2(acc[jj][1][0], wp.y, v0);
                        FMA2(acc[jj][0][1], wp.x, v1); FMA2(acc[jj][1][1], wp.y, v1);
                        FMA2(acc[jj][0][2], wp.x, v2); FMA2(acc[jj][1][2], wp.y, v2);
                        FMA2(acc[jj][0][3], wp.x, v3); FMA2(acc[jj][1][3], wp.y, v3);
                    }
                }
            }
        }
    }

    #pragma unroll
    for (int jj = 0; jj < 2; jj++)
        #pragma unroll
        for (int h = 0; h < 2; h++) {
            int oc = oc0 + ocw + 4*jj + 2*h;
            float b0 = bias[oc], b1 = bias[oc + 1];
            #pragma unroll
            for (int py = 0; py < 4; py++) {
                float2 f = unpack2(acc[jj][h][py]);
                int oy = oy0 + py;
                g_h2[((size_t)(b*256 + oc    )*32 + oy)*32 + lane] = fmaxf(f.x + b0, 0.f);
                g_h2[((size_t)(b*256 + oc + 1)*32 + oy)*32 + lane] = fmaxf(f.y + b1, 0.f);
            }
        }
}

// ---------------- res3: conv3x3(relu(h2))+b -> g_r (f32x2) ------------------
// grid (64, 8), block 128. oc tile 32, px tile 32x4.
__global__ void __launch_bounds__(128) k_res3(const float* __restrict__ w,
                                              const float* __restrict__ bias)
{
    int b   = blockIdx.x >> 3;
    int oy0 = (blockIdx.x & 7) * 4;
    int oc0 = blockIdx.y * 32;
    int tid = threadIdx.x;
    int lane = tid & 31, warp = tid >> 5;
    int ocw = warp * 8;

    __shared__ __align__(16) float2 s_in[8][6][34];  // dup, j -> ix=j-1
    __shared__ __align__(16) float  s_w[8][9][36];

    u64 acc[2][2][4] = {};

    for (int c0 = 0; c0 < 256; c0 += 8) {
        __syncthreads();
        for (int e = tid; e < 8*6*34; e += 128) {
            int c = e / 204, rem = e % 204;
            int r = rem / 34, j = rem % 34;
            int ix = j - 1, iy = oy0 - 1 + r;
            float v = 0.f;
            if (iy >= 0 && iy < 32 && ix >= 0 && ix < 32)
                v = fmaxf(g_h2[((size_t)(b*256 + c0 + c)*32 + iy)*32 + ix], 0.f);
            s_in[c][r][j] = make_float2(v, v);
        }
        for (int e = tid; e < 2304; e += 128) {
            int o = e / 72, rem = e % 72;
            int c = rem / 9, tap = rem % 9;
            s_w[c][tap][o] = w[(size_t)(oc0 + o)*2304 + (c0 + c)*9 + tap];
        }
        __syncthreads();

        #pragma unroll 1
        for (int c = 0; c < 8; c++) {
            #pragma unroll
            for (int ky = 0; ky < 3; ky++) {
                #pragma unroll
                for (int kx = 0; kx < 3; kx++) {
                    u64 v0 = *(const u64*)&s_in[c][0 + ky][lane + kx];
                    u64 v1 = *(const u64*)&s_in[c][1 + ky][lane + kx];
                    u64 v2 = *(const u64*)&s_in[c][2 + ky][lane + kx];
                    u64 v3 = *(const u64*)&s_in[c][3 + ky][lane + kx];
                    #pragma unroll
                    for (int jj = 0; jj < 2; jj++) {
                        ulonglong2 wp = *(const ulonglong2*)&s_w[c][ky*3 + kx][ocw + 4*jj];
                        FMA2(acc[jj][0][0], wp.x, v0); FMA2(acc[jj][1][0], wp.y, v0);
                        FMA2(acc[jj][0][1], wp.x, v1); FMA2(acc[jj][1][1], wp.y, v1);
                        FMA2(acc[jj][0][2], wp.x, v2); FMA2(acc[jj][1][2], wp.y, v2);
                        FMA2(acc[jj][0][3], wp.x, v3); FMA2(acc[jj][1][3], wp.y, v3);
                    }
                }
            }
        }
    }

    #pragma unroll
    for (int jj = 0; jj < 2; jj++)
        #pragma unroll
        for (int h = 0; h < 2; h++) {
            int oc = oc0 + ocw + 4*jj + 2*h;
            float b0 = bias[oc], b1 = bias[oc + 1];
            #pragma unroll
            for (int py = 0; py < 4; py++) {
                float2 f = unpack2(acc[jj][h][py]);
                int oy = oy0 + py;
                g_r[((size_t)(b*256 + oc    )*32 + oy)*32 + lane] = f.x + b0;
                g_r[((size_t)(b*256 + oc + 1)*32 + oy)*32 + lane] = f.y + b1;
            }
        }
}

// ---------------- conv1x1 GEMM (unchanged) ----------------------------------
template<int CIN, int INRELU, int OUTRELU, int ADDRES>
__global__ void k_conv1(const float* __restrict__ in, const float* __restrict__ w,
                        const float* __restrict__ bias, const float* __restrict__ res,
                        float* __restrict__ out, float* __restrict__ out2, int cout)
{
    int b  = blockIdx.x >> 3;
    int pt = blockIdx.x & 7;
    int oc0 = blockIdx.y * 64;
    int tx = threadIdx.x, ty = threadIdx.y;
    int tid = ty * 32 + tx;
    int px0 = pt * 128;

    __shared__ float s_in[16][128];
    __shared__ float s_w[64][16];

    float acc[8][4];
    #pragma unroll
    for (int j = 0; j < 8; j++)
        #pragma unroll
        for (int m = 0; m < 4; m++) acc[j][m] = 0.f;

    for (int c0 = 0; c0 < CIN; c0 += 16) {
        __syncthreads();
        for (int e = tid; e < 2048; e += 256) {
            int i = e >> 7, p = e & 127;
            float v = in[(size_t)(b*CIN + c0 + i)*1024 + px0 + p];
            if (INRELU) v = fmaxf(v, 0.f);
            s_in[i][p] = v;
        }
        for (int e = tid; e < 1024; e += 256)
            s_w[e >> 4][e & 15] = w[(size_t)(oc0 + (e >> 4))*CIN + c0 + (e & 15)];
        __syncthreads();

        #pragma unroll
        for (int i = 0; i < 16; i++) {
            float v0 = s_in[i][tx], v1 = s_in[i][tx+32];
            float v2 = s_in[i][tx+64], v3 = s_in[i][tx+96];
            #pragma unroll
            for (int j = 0; j < 8; j++) {
                float wv = s_w[ty*8 + j][i];
                acc[j][0] += wv*v0; acc[j][1] += wv*v1;
                acc[j][2] += wv*v2; acc[j][3] += wv*v3;
            }
        }
    }

    #pragma unroll
    for (int j = 0; j < 8; j++) {
        int oc = oc0 + ty*8 + j;
        float bv = bias[oc];
        #pragma unroll
        for (int m = 0; m < 4; m++) {
            size_t idx = (size_t)(b*cout + oc)*1024 + px0 + tx + 32*m;
            float v = acc[j][m] + bv;
            if (ADDRES) v += res[idx];
            if (OUTRELU) v = fmaxf(v, 0.f);
            out[idx] = v;
            if (out2) out2[idx] = v;
        }
    }
}

// ---------------- VQ (unchanged) --------------------------------------------
__global__ void k_vq(const float* __restrict__ codebook, float* __restrict__ d_out)
{
    int pos = blockIdx.x * 128 + threadIdx.x;
    int b = pos >> 10, hw = pos & 1023;

    float z[64], z2 = 0.f;
    #pragma unroll
    for (int c = 0; c < 64; c++) {
        z[c] = g_z[(size_t)(b*64 + c)*1024 + hw];
        z2 += z[c]*z[c];
    }

    __shared__ float s_cb[128][64];
    __shared__ float s_n[128];

    float best = INFINITY; int bestk = 0;
    for (int k0 = 0; k0 < 512; k0 += 128) {
        __syncthreads();
        for (int e = threadIdx.x; e < 8192; e += 128)
            s_cb[e >> 6][e & 63] = codebook[k0*64 + e];
        __syncthreads();
        {
            float n = 0.f;
            #pragma unroll
            for (int c = 0; c < 64; c++) { float cv = s_cb[threadIdx.x][c]; n += cv*cv; }
            s_n[threadIdx.x] = n;
        }
        __syncthreads();
        for (int k = 0; k < 128; k++) {
            float dot = 0.f;
            #pragma unroll
            for (int c = 0; c < 64; c++) dot += z[c]*s_cb[k][c];
            float d = (z2 - 2.f*dot) + s_n[k];
            if (d < best) { best = d; bestk = k0 + k; }
        }
    }

    d_out[IDS_OFF + pos] = (float)bestk;
    const float* crow = codebook + (size_t)bestk*64;
    #pragma unroll
    for (int c = 0; c < 64; c++) {
        float v = crow[c];
        size_t idx = (size_t)(b*64 + c)*1024 + hw;
        g_ek[idx] = v;
        d_out[EK_OFF + idx] = v;
    }
}

// ---------------- t1: convT 256->256 k4 s2 p1, 32->64, relu (f32x2) ---------
// grid (128, 8), block 128. oc tile 32, row tile 4, each thread 8 ox x 8 oc.
__global__ void __launch_bounds__(128) k_t1(const float* __restrict__ w,
                                            const float* __restrict__ bias)
{
    int b   = blockIdx.x >> 4;
    int oy0 = (blockIdx.x & 15) * 4;
    int oc0 = blockIdx.y * 32;
    int tid = threadIdx.x;
    int lane = tid & 31, warp = tid >> 5;
    int ocw = warp * 8;
    int q   = lane & 7;          // ox octet 8q..8q+7
    int oyl = lane >> 3;
    int oy  = oy0 + oyl;

    int kyA, kyB;
    if (oy & 1) { kyA = 0; kyB = 2; } else { kyA = 1; kyB = 3; }

    __shared__ __align__(16) float2 s_in[8][4][2][34]; // [ic][oyl][rr][j] dup, ix=j-1
    __shared__ __align__(16) float  s_w[8][16][36];    // [ic][tap][oc] pad36

    u64 accE[2][2][4] = {}, accO[2][2][4] = {};

    for (int c0 = 0; c0 < 256; c0 += 8) {
        __syncthreads();
        for (int e = tid; e < 2176; e += 128) {
            int c = e / 272, rem = e % 272;
            int ol = rem / 68;
            int rr = (rem / 34) & 1;
            int j = rem % 34;
            int ix = j - 1;
            int o_y = oy0 + ol;
            int iy;
            if (o_y & 1) iy = rr ? ((o_y - 1) >> 1) : ((o_y + 1) >> 1);
            else         iy = rr ? ((o_y >> 1) - 1) : (o_y >> 1);
            float v = 0.f;
            if (iy >= 0 && iy < 32 && ix >= 0 && ix < 32)
                v = g_r[((size_t)(b*256 + c0 + c)*32 + iy)*32 + ix];
            s_in[c][ol][rr][j] = make_float2(v, v);
        }
        for (int e = tid; e < 1024; e += 128) {
            int o = e >> 5, c = (e >> 2) & 7, t4 = (e & 3) * 4;
            float4 wv = *(const float4*)&w[(size_t)(c0 + c)*4096 + (oc0 + o)*16 + t4];
            s_w[c][t4+0][o] = wv.x; s_w[c][t4+1][o] = wv.y;
            s_w[c][t4+2][o] = wv.z; s_w[c][t4+3][o] = wv.w;
        }
        __syncthreads();

        #pragma unroll 1
        for (int c = 0; c < 8; c++) {
            #pragma unroll
            for (int rr = 0; rr < 2; rr++) {
                int ky = rr ? kyB : kyA;
                u64 v[6];
                #pragma unroll
                for (int i = 0; i < 6; i++)
                    v[i] = *(const u64*)&s_in[c][oyl][rr][4*q + i];
                #pragma unroll
                for (int jj = 0; jj < 2; jj++) {
                    ulonglong2 W0 = *(const ulonglong2*)&s_w[c][ky*4 + 0][ocw + 4*jj];
                    ulonglong2 W1 = *(const ulonglong2*)&s_w[c][ky*4 + 1][ocw + 4*jj];
                    ulonglong2 W2 = *(const ulonglong2*)&s_w[c][ky*4 + 2][ocw + 4*jj];
                    ulonglong2 W3 = *(const ulonglong2*)&s_w[c][ky*4 + 3][ocw + 4*jj];
                    #pragma unroll
                    for (int t = 0; t < 4; t++) {
                        // even ox=8q+2t: w[ky,3]*in[i=t(ix=4q+t-1)] + w[ky,1]*in[t+1]
                        FMA2(accE[jj][0][t], W3.x, v[t]);
                        FMA2(accE[jj][0][t], W1.x, v[t + 1]);
                        FMA2(accE[jj][1][t], W3.y, v[t]);
                        FMA2(accE[jj][1][t], W1.y, v[t + 1]);
                        // odd ox=8q+2t+1: w[ky,0]*in[t+2] + w[ky,2]*in[t+1]
                        FMA2(accO[jj][0][t], W0.x, v[t + 2]);
                        FMA2(accO[jj][0][t], W2.x, v[t + 1]);
                        FMA2(accO[jj][1][t], W0.y, v[t + 2]);
                        FMA2(accO[jj][1][t], W2.y, v[t + 1]);
                    }
                }
            }
        }
    }

    #pragma unroll
    for (int jj = 0; jj < 2; jj++)
        #pragma unroll
        for (int h = 0; h < 2; h++) {
            int oc = oc0 + ocw + 4*jj + 2*h;
            float b0 = bias[oc], b1 = bias[oc + 1];
            #pragma unroll
            for (int t = 0; t < 4; t++) {
                float2 fe = unpack2(accE[jj][h][t]);
                float2 fo = unpack2(accO[jj][h][t]);
                int ox = 8*q + 2*t;
                size_t base0 = ((size_t)(b*256 + oc    )*64 + oy)*64;
                size_t base1 = ((size_t)(b*256 + oc + 1)*64 + oy)*64;
                g_h1[base0 + ox]     = fmaxf(fe.x + b0, 0.f);
                g_h1[base1 + ox]     = fmaxf(fe.y + b1, 0.f);
                g_h1[base0 + ox + 1] = fmaxf(fo.x + b0, 0.f);
                g_h1[base1 + ox + 1] = fmaxf(fo.y + b1, 0.f);
            }
        }
}

// ---------------- t2: convT 256->3 k4 s2 p1, 64->128, sigmoid (small) -------
__global__ void k_t2(const float* __restrict__ w, const float* __restrict__ bias,
                     float* __restrict__ out)
{
    int b  = blockIdx.x >> 7;
    int oy = blockIdx.x & 127;
    int tx = threadIdx.x;

    int iy0, ky0, iy1, ky1;
    if (oy & 1) { iy0 = (oy + 1) >> 1; ky0 = 0; iy1 = (oy - 1) >> 1; ky1 = 2; }
    else        { iy0 = oy >> 1;       ky0 = 1; iy1 = (oy >> 1) - 1; ky1 = 3; }

    __shared__ float s_in[16][2][66];
    __shared__ float s_w[16][3][16];

    float acc[3][2];
    #pragma unroll
    for (int o = 0; o < 3; o++) { acc[o][0] = 0.f; acc[o][1] = 0.f; }

    for (int c0 = 0; c0 < 256; c0 += 16) {
        __syncthreads();
        for (int e = tx; e < 2112; e += 64) {
            int c = e / 132, rem = e % 132;
            int rr = rem / 66, col = rem % 66;
            int iy = rr ? iy1 : iy0, ix = col - 1;
            float v = 0.f;
            if (iy >= 0 && iy < 64 && ix >= 0 && ix < 64)
                v = g_h1[((size_t)(b*256 + c0 + c)*64 + iy)*64 + ix];
            s_in[c][rr][col] = v;
        }
        for (int e = tx; e < 768; e += 64) {
            int c = e / 48, rem = e % 48;
            s_w[c][rem / 16][rem % 16] = w[((size_t)(c0 + c)*3 + rem/16)*16 + rem%16];
        }
        __syncthreads();

        #pragma unroll
        for (int c = 0; c < 16; c++)
            #pragma unroll
            for (int rr = 0; rr < 2; rr++) {
                float a  = s_in[c][rr][tx];
                float bb = s_in[c][rr][tx + 1];
                float cc = s_in[c][rr][tx + 2];
                int ky = rr ? ky1 : ky0;
                #pragma unroll
                for (int o = 0; o < 3; o++) {
                    const float* wr = s_w[c][o];
                    acc[o][0] += wr[ky*4 + 3]*a  + wr[ky*4 + 1]*bb;
                    acc[o][1] += wr[ky*4 + 0]*cc + wr[ky*4 + 2]*bb;
                }
            }
    }

    #pragma unroll
    for (int o = 0; o < 3; o++) {
        float bv = bias[o];
        #pragma unroll
        for (int p = 0; p < 2; p++) {
            float v = acc[o][p] + bv;
            out[((size_t)(b*3 + o)*128 + oy)*128 + 2*tx + p] = 1.f / (1.f + expf(-v));
        }
    }
}

// ---------------- launch ----------------------------------------------------
extern "C" void kernel_launch(void* const* d_in, const int* in_sizes, int n_in,
                              void* d_out, int out_size)
{
    const float* x        = (const float*)d_in[0];
    const float* c1_w     = (const float*)d_in[1];
    const float* c1_b     = (const float*)d_in[2];
    const float* c2_w     = (const float*)d_in[3];
    const float* c2_b     = (const float*)d_in[4];
    const float* r0_w3    = (const float*)d_in[5];
    const float* r0_b3    = (const float*)d_in[6];
    const float* r0_w1    = (const float*)d_in[7];
    const float* r0_b1    = (const float*)d_in[8];
    const float* r1_w3    = (const float*)d_in[9];
    const float* r1_b3    = (const float*)d_in[10];
    const float* r1_w1    = (const float*)d_in[11];
    const float* r1_b1    = (const float*)d_in[12];
    const float* to_z_w   = (const float*)d_in[13];
    const float* to_z_b   = (const float*)d_in[14];
    const float* codebook = (const float*)d_in[15];
    const float* from_z_w = (const float*)d_in[16];
    const float* from_z_b = (const float*)d_in[17];
    const float* t1_w     = (const float*)d_in[18];
    const float* t1_b     = (const float*)d_in[19];
    const float* t2_w     = (const float*)d_in[20];
    const float* t2_b     = (const float*)d_in[21];

    float* out = (float*)d_out;

    float *p_h2, *p_r, *p_z, *p_ek;
    cudaGetSymbolAddress((void**)&p_h2, g_h2);
    cudaGetSymbolAddress((void**)&p_r,  g_r);
    cudaGetSymbolAddress((void**)&p_z,  g_z);
    cudaGetSymbolAddress((void**)&p_ek, g_ek);

    k_c1<<<dim3(B*64, 16), dim3(64, 4)>>>(x, c1_w, c1_b);
    k_c2<<<dim3(64, 8), 128>>>(c2_w, c2_b);

    k_res3<<<dim3(64, 8), 128>>>(r0_w3, r0_b3);
    k_conv1<256, 1, 0, 1><<<dim3(B*8, 4), dim3(32, 8)>>>(
        p_r, r0_w1, r0_b1, p_h2, p_h2, nullptr, 256);
    k_res3<<<dim3(64, 8), 128>>>(r1_w3, r1_b3);
    k_conv1<256, 1, 0, 1><<<dim3(B*8, 4), dim3(32, 8)>>>(
        p_r, r1_w1, r1_b1, p_h2, p_h2, nullptr, 256);

    k_conv1<256, 0, 0, 0><<<dim3(B*8, 1), dim3(32, 8)>>>(
        p_h2, to_z_w, to_z_b, nullptr, p_z, out + ZE_OFF, 64);

    k_vq<<<64, 128>>>(codebook, out);

    k_conv1<64, 0, 1, 0><<<dim3(B*8, 4), dim3(32, 8)>>>(
        p_ek, from_z_w, from_z_b, nullptr, p_r, nullptr, 256);
    k_t1<<<dim3(128, 8), 128>>>(t1_w, t1_b);
    k_t2<<<dim3(B*128), 64>>>(t2_w, t2_b, out);

    (void)in_sizes; (void)n_in; (void)out_size;
}